// round 1
// baseline (speedup 1.0000x reference)
#include <cuda_runtime.h>

#define N_NODES 100000
#define NFEAT   256
#define NHID    256
#define NCLASS  64

// ---------------- scratch (device globals; no runtime allocation) ----------------
__device__ float g_buf0[(size_t)N_NODES * NHID];   // support / layer activations
__device__ float g_buf1[(size_t)N_NODES * NHID];
__device__ float g_headW[NHID * 2 * NCLASS];       // packed [WL1 | WL2], 256 x 128
__device__ float g_headb[2 * NCLASS];
__device__ int   g_row_ptr[N_NODES + 1];

// ---------------- CSR row_ptr from sorted edge_dst (binary search) ----------------
__global__ void build_row_ptr_kernel(const int* __restrict__ dst, int n_edges) {
    int i = blockIdx.x * blockDim.x + threadIdx.x;
    if (i > N_NODES) return;
    int lo = 0, hi = n_edges;
    while (lo < hi) {
        int mid = (lo + hi) >> 1;
        if (dst[mid] < i) lo = mid + 1; else hi = mid;
    }
    g_row_ptr[i] = lo;
}

// ---------------- pack twin-head weights into one 256x128 matrix ----------------
__global__ void pack_head_kernel(const float* __restrict__ WL1, const float* __restrict__ WL2,
                                 const float* __restrict__ bL1, const float* __restrict__ bL2) {
    int i = blockIdx.x * blockDim.x + threadIdx.x;
    if (i < NHID * 2 * NCLASS) {
        int k = i / (2 * NCLASS), c = i % (2 * NCLASS);
        g_headW[i] = (c < NCLASS) ? WL1[k * NCLASS + c] : WL2[k * NCLASS + (c - NCLASS)];
    }
    if (i < 2 * NCLASS)
        g_headb[i] = (i < NCLASS) ? bL1[i] : bL2[i - NCLASS];
}

// ---------------- 128x128x16 tiled fp32 GEMM: C = A @ B ----------------
// A: MxK row-major, B: KxN row-major, C: MxN row-major. K%16==0, N%128==0.
__global__ void sgemm_kernel(const float* __restrict__ A, const float* __restrict__ B,
                             float* __restrict__ C, int M, int K, int N) {
    __shared__ float As[16][128 + 4];   // transposed A tile
    __shared__ float Bs[16][128];
    const int tid = threadIdx.x;
    const int tx = tid & 15, ty = tid >> 4;
    const int m0 = blockIdx.y * 128, n0 = blockIdx.x * 128;

    float acc[8][8];
#pragma unroll
    for (int i = 0; i < 8; i++)
#pragma unroll
        for (int j = 0; j < 8; j++) acc[i][j] = 0.f;

    for (int k0 = 0; k0 < K; k0 += 16) {
        // A tile: 128 rows x 16 cols  (2 passes of 256 threads x float4)
#pragma unroll
        for (int p = 0; p < 2; p++) {
            int row = (tid >> 2) + p * 64;
            int col = (tid & 3) * 4;
            float4 v = make_float4(0.f, 0.f, 0.f, 0.f);
            if (m0 + row < M)
                v = *(const float4*)(A + (size_t)(m0 + row) * K + k0 + col);
            As[col + 0][row] = v.x; As[col + 1][row] = v.y;
            As[col + 2][row] = v.z; As[col + 3][row] = v.w;
        }
        // B tile: 16 rows x 128 cols
#pragma unroll
        for (int p = 0; p < 2; p++) {
            int row = (tid >> 5) + p * 8;
            int col = (tid & 31) * 4;
            *(float4*)&Bs[row][col] =
                *(const float4*)(B + (size_t)(k0 + row) * N + n0 + col);
        }
        __syncthreads();

#pragma unroll
        for (int k = 0; k < 16; k++) {
            float a[8], b[8];
#pragma unroll
            for (int i = 0; i < 8; i++) a[i] = As[k][ty * 8 + i];
#pragma unroll
            for (int j = 0; j < 8; j++) b[j] = Bs[k][tx * 8 + j];
#pragma unroll
            for (int i = 0; i < 8; i++)
#pragma unroll
                for (int j = 0; j < 8; j++)
                    acc[i][j] += a[i] * b[j];
        }
        __syncthreads();
    }

#pragma unroll
    for (int i = 0; i < 8; i++) {
        int row = m0 + ty * 8 + i;
        if (row >= M) continue;
#pragma unroll
        for (int j = 0; j < 8; j += 4) {
            float4 v = make_float4(acc[i][j], acc[i][j + 1], acc[i][j + 2], acc[i][j + 3]);
            *(float4*)(C + (size_t)row * N + n0 + tx * 8 + j) = v;
        }
    }
}

// ---------------- head GEMM: logits = h @ [WL1|WL2] + [bL1|bL2], split store ----------------
__global__ void head_gemm_kernel(const float* __restrict__ A, float* __restrict__ out, int M) {
    const int K = NHID, N = 2 * NCLASS;  // 256, 128
    __shared__ float As[16][128 + 4];
    __shared__ float Bs[16][128];
    const int tid = threadIdx.x;
    const int tx = tid & 15, ty = tid >> 4;
    const int m0 = blockIdx.y * 128;

    float acc[8][8];
#pragma unroll
    for (int i = 0; i < 8; i++)
#pragma unroll
        for (int j = 0; j < 8; j++) acc[i][j] = 0.f;

    for (int k0 = 0; k0 < K; k0 += 16) {
#pragma unroll
        for (int p = 0; p < 2; p++) {
            int row = (tid >> 2) + p * 64;
            int col = (tid & 3) * 4;
            float4 v = make_float4(0.f, 0.f, 0.f, 0.f);
            if (m0 + row < M)
                v = *(const float4*)(A + (size_t)(m0 + row) * K + k0 + col);
            As[col + 0][row] = v.x; As[col + 1][row] = v.y;
            As[col + 2][row] = v.z; As[col + 3][row] = v.w;
        }
#pragma unroll
        for (int p = 0; p < 2; p++) {
            int row = (tid >> 5) + p * 8;
            int col = (tid & 31) * 4;
            *(float4*)&Bs[row][col] =
                *(const float4*)(g_headW + (size_t)(k0 + row) * N + col);
        }
        __syncthreads();

#pragma unroll
        for (int k = 0; k < 16; k++) {
            float a[8], b[8];
#pragma unroll
            for (int i = 0; i < 8; i++) a[i] = As[k][ty * 8 + i];
#pragma unroll
            for (int j = 0; j < 8; j++) b[j] = Bs[k][tx * 8 + j];
#pragma unroll
            for (int i = 0; i < 8; i++)
#pragma unroll
                for (int j = 0; j < 8; j++)
                    acc[i][j] += a[i] * b[j];
        }
        __syncthreads();
    }

#pragma unroll
    for (int i = 0; i < 8; i++) {
        int row = m0 + ty * 8 + i;
        if (row >= M) continue;
#pragma unroll
        for (int j = 0; j < 8; j += 4) {
            int col = tx * 8 + j;                       // 0..124, 4-aligned -> never straddles 64
            float4 v = make_float4(acc[i][j]     + g_headb[col],
                                   acc[i][j + 1] + g_headb[col + 1],
                                   acc[i][j + 2] + g_headb[col + 2],
                                   acc[i][j + 3] + g_headb[col + 3]);
            float* base = (col < NCLASS)
                ? out + (size_t)row * NCLASS + col
                : out + (size_t)N_NODES * NCLASS + (size_t)row * NCLASS + (col - NCLASS);
            *(float4*)base = v;
        }
    }
}

// ---------------- SpMM + bias + relu: H[dst] = relu(sum_e w*S[src] + b) ----------------
// One warp per destination node; 256-float accumulator = 8 regs/lane.
__global__ void spmm_relu_kernel(const float* __restrict__ S, const int* __restrict__ src,
                                 const float* __restrict__ w, const float* __restrict__ bias,
                                 float* __restrict__ H) {
    int node = (blockIdx.x * blockDim.x + threadIdx.x) >> 5;
    if (node >= N_NODES) return;
    int lane = threadIdx.x & 31;
    int e0 = g_row_ptr[node], e1 = g_row_ptr[node + 1];

    float4 acc0 = make_float4(0.f, 0.f, 0.f, 0.f);
    float4 acc1 = make_float4(0.f, 0.f, 0.f, 0.f);

#pragma unroll 2
    for (int e = e0; e < e1; e++) {
        int   s  = __ldg(src + e);
        float ww = __ldg(w + e);
        const float4* row = (const float4*)(S + (size_t)s * NHID);
        float4 a = __ldg(row + lane);
        float4 b = __ldg(row + lane + 32);
        acc0.x += ww * a.x; acc0.y += ww * a.y; acc0.z += ww * a.z; acc0.w += ww * a.w;
        acc1.x += ww * b.x; acc1.y += ww * b.y; acc1.z += ww * b.z; acc1.w += ww * b.w;
    }

    const float4* bp = (const float4*)bias;
    float4 b0 = bp[lane], b1 = bp[lane + 32];
    acc0.x = fmaxf(acc0.x + b0.x, 0.f); acc0.y = fmaxf(acc0.y + b0.y, 0.f);
    acc0.z = fmaxf(acc0.z + b0.z, 0.f); acc0.w = fmaxf(acc0.w + b0.w, 0.f);
    acc1.x = fmaxf(acc1.x + b1.x, 0.f); acc1.y = fmaxf(acc1.y + b1.y, 0.f);
    acc1.z = fmaxf(acc1.z + b1.z, 0.f); acc1.w = fmaxf(acc1.w + b1.w, 0.f);

    float4* o = (float4*)(H + (size_t)node * NHID);
    o[lane] = acc0;
    o[lane + 32] = acc1;
}

// ---------------- launch ----------------
extern "C" void kernel_launch(void* const* d_in, const int* in_sizes, int n_in,
                              void* d_out, int out_size) {
    const float* x   = (const float*)d_in[0];
    const int*   es  = (const int*)  d_in[1];
    const int*   ed  = (const int*)  d_in[2];
    const float* ew  = (const float*)d_in[3];
    const float* W1  = (const float*)d_in[4];
    const float* b1  = (const float*)d_in[5];
    const float* W2  = (const float*)d_in[6];
    const float* b2  = (const float*)d_in[7];
    const float* WL1 = (const float*)d_in[8];
    const float* bL1 = (const float*)d_in[9];
    const float* WL2 = (const float*)d_in[10];
    const float* bL2 = (const float*)d_in[11];
    int n_edges = in_sizes[1];

    float *buf0, *buf1;
    cudaGetSymbolAddress((void**)&buf0, g_buf0);
    cudaGetSymbolAddress((void**)&buf1, g_buf1);

    build_row_ptr_kernel<<<(N_NODES + 256) / 256, 256>>>(ed, n_edges);
    pack_head_kernel<<<(NHID * 2 * NCLASS + 255) / 256, 256>>>(WL1, WL2, bL1, bL2);

    dim3 gemm_grid(NHID / 128, (N_NODES + 127) / 128);
    const int spmm_blocks = (N_NODES + 7) / 8;  // 8 warps / block

    // layer 1
    sgemm_kernel<<<gemm_grid, 256>>>(x, W1, buf0, N_NODES, NFEAT, NHID);
    spmm_relu_kernel<<<spmm_blocks, 256>>>(buf0, es, ew, b1, buf1);
    // layer 2
    sgemm_kernel<<<gemm_grid, 256>>>(buf1, W2, buf0, N_NODES, NHID, NHID);
    spmm_relu_kernel<<<spmm_blocks, 256>>>(buf0, es, ew, b2, buf1);
    // twin heads (fused)
    head_gemm_kernel<<<dim3(1, (N_NODES + 127) / 128), 256>>>(buf1, (float*)d_out, N_NODES);
}

// round 3
// speedup vs baseline: 1.4861x; 1.4861x over previous
#include <cuda_runtime.h>
#include <cuda_bf16.h>
#include <cstdint>

#define N_NODES 100000
#define NFEAT   256
#define NHID    256
#define NCLASS  64
#define KDIM    256

// ---------------- scratch (device globals; no runtime allocation) ----------------
__device__ __align__(128) float         g_S[(size_t)N_NODES * NHID];     // fp32 GEMM out / SpMM in
__device__ __align__(128) __nv_bfloat16 g_xh[(size_t)N_NODES * NFEAT];
__device__ __align__(128) __nv_bfloat16 g_xl[(size_t)N_NODES * NFEAT];
__device__ __align__(128) __nv_bfloat16 g_hh[(size_t)N_NODES * NHID];
__device__ __align__(128) __nv_bfloat16 g_hl[(size_t)N_NODES * NHID];
__device__ __align__(128) __nv_bfloat16 g_w1t_h[KDIM * NHID], g_w1t_l[KDIM * NHID]; // W1^T [N,K]
__device__ __align__(128) __nv_bfloat16 g_w2t_h[KDIM * NHID], g_w2t_l[KDIM * NHID]; // W2^T
__device__ __align__(128) __nv_bfloat16 g_wht_h[128 * KDIM],  g_wht_l[128 * KDIM];  // [WL1|WL2]^T
__device__ float g_headb[2 * NCLASS];
__device__ int   g_row_ptr[N_NODES + 1];

// ---------------- small PTX helpers ----------------
__device__ __forceinline__ void cp16(uint32_t s, const __nv_bfloat16* g, bool v) {
    int sz = v ? 16 : 0;
    asm volatile("cp.async.cg.shared.global [%0], [%1], 16, %2;"
                 :: "r"(s), "l"(__cvta_generic_to_global(g)), "r"(sz));
}
#define CP_COMMIT() asm volatile("cp.async.commit_group;" ::: "memory")

__device__ __forceinline__ void ldsm4(uint32_t* r, uint32_t a) {
    asm volatile("ldmatrix.sync.aligned.m8n8.x4.shared.b16 {%0,%1,%2,%3}, [%4];"
                 : "=r"(r[0]), "=r"(r[1]), "=r"(r[2]), "=r"(r[3]) : "r"(a));
}
__device__ __forceinline__ void mma16816(float* c, const uint32_t* a, const uint32_t* b) {
    asm volatile("mma.sync.aligned.m16n8k16.row.col.f32.bf16.bf16.f32 "
                 "{%0,%1,%2,%3}, {%4,%5,%6,%7}, {%8,%9}, {%0,%1,%2,%3};"
                 : "+f"(c[0]), "+f"(c[1]), "+f"(c[2]), "+f"(c[3])
                 : "r"(a[0]), "r"(a[1]), "r"(a[2]), "r"(a[3]), "r"(b[0]), "r"(b[1]));
}

// ---------------- CSR row_ptr from sorted edge_dst ----------------
__global__ void build_row_ptr_kernel(const int* __restrict__ dst, int n_edges) {
    int i = blockIdx.x * blockDim.x + threadIdx.x;
    if (i > N_NODES) return;
    int lo = 0, hi = n_edges;
    while (lo < hi) {
        int mid = (lo + hi) >> 1;
        if (dst[mid] < i) lo = mid + 1; else hi = mid;
    }
    g_row_ptr[i] = lo;
}

// ---------------- weight prep: transpose + bf16 split ----------------
__device__ __forceinline__ void split_store(__nv_bfloat16* ph, __nv_bfloat16* pl, float v) {
    __nv_bfloat16 hi = __float2bfloat16(v);
    *ph = hi;
    *pl = __float2bfloat16(v - __bfloat162float(hi));
}
__global__ void prep_w_kernel(const float* __restrict__ W1, const float* __restrict__ W2,
                              const float* __restrict__ WL1, const float* __restrict__ WL2,
                              const float* __restrict__ bL1, const float* __restrict__ bL2) {
    int i = blockIdx.x * blockDim.x + threadIdx.x;
    if (i < KDIM * NHID) {
        int n = i >> 8, k = i & 255;
        split_store(&g_w1t_h[i], &g_w1t_l[i], W1[k * NHID + n]);
        split_store(&g_w2t_h[i], &g_w2t_l[i], W2[k * NHID + n]);
    }
    if (i < 128 * KDIM) {
        int n = i >> 8, k = i & 255;
        float v = (n < NCLASS) ? WL1[k * NCLASS + n] : WL2[k * NCLASS + (n - NCLASS)];
        split_store(&g_wht_h[i], &g_wht_l[i], v);
    }
    if (i < 2 * NCLASS)
        g_headb[i] = (i < NCLASS) ? bL1[i] : bL2[i - NCLASS];
}

// ---------------- x -> bf16 hi/lo ----------------
__global__ void convert_x_kernel(const float* __restrict__ x) {
    int i = blockIdx.x * blockDim.x + threadIdx.x;
    if (i >= N_NODES * NFEAT) return;
    split_store(&g_xh[i], &g_xl[i], x[i]);
}

// ---------------- mma.sync split-bf16 GEMM ----------------
// C[M, ldC-chunk] = (Ah+Al) @ (Bh+Bl)^T  via AhBh + AhBl + AlBh, fp32 accum.
// A: [M,256] bf16 row-major; B: [Nrows,256] bf16 row-major (= W^T, K-major).
// CTA tile 128x128, K-chunk 64, 2-stage cp.async pipeline.
constexpr int KC     = 64;
constexpr int ROWB   = 144;            // (64+8) halves * 2B, 16B aligned, conflict-free
constexpr int TILEB  = 128 * ROWB;     // 18432
constexpr int STAGEB = 4 * TILEB;      // 73728  (tiles: Ah, Al, Bh, Bl)
constexpr int GEMM_SMEM = 2 * STAGEB;  // 147456

template <bool HEAD>
__global__ void __launch_bounds__(256, 1) gemm_mma_kernel(
    const __nv_bfloat16* __restrict__ Ah, const __nv_bfloat16* __restrict__ Al,
    const __nv_bfloat16* __restrict__ Bh, const __nv_bfloat16* __restrict__ Bl,
    float* __restrict__ out, int M, int ldC)
{
    extern __shared__ __align__(128) char smem[];
    const int tid = threadIdx.x, lane = tid & 31, wid = tid >> 5;
    const int wm = wid >> 2, wn = wid & 3;            // 2(M) x 4(N) warps, warp tile 64x32
    const int m0 = blockIdx.y * 128;
    const int n0 = blockIdx.x * 128;
    const __nv_bfloat16* BhO = Bh + (size_t)n0 * KDIM;
    const __nv_bfloat16* BlO = Bl + (size_t)n0 * KDIM;
    uint32_t sb = (uint32_t)__cvta_generic_to_shared(smem);

    float acc[4][4][4];
#pragma unroll
    for (int a = 0; a < 4; a++)
#pragma unroll
        for (int b = 0; b < 4; b++)
#pragma unroll
            for (int c = 0; c < 4; c++) acc[a][b][c] = 0.f;

    // ---- stage loader: 4 tiles x 128 rows x 4 chunks(16B) = 2048... (8 chunks of 8 halves) ----
    auto load_stage = [&](int stage, int kc) {
        uint32_t base = sb + stage * STAGEB;
        for (int i = tid; i < 4096; i += 256) {
            int t = i >> 10, rc = i & 1023, r = rc >> 3, ch = rc & 7;
            const __nv_bfloat16* src;
            bool v = true;
            if (t == 0)      { src = Ah  + (size_t)(m0 + r) * KDIM + kc + ch * 8; v = (m0 + r) < M; }
            else if (t == 1) { src = Al  + (size_t)(m0 + r) * KDIM + kc + ch * 8; v = (m0 + r) < M; }
            else if (t == 2) { src = BhO + (size_t)r * KDIM + kc + ch * 8; }
            else             { src = BlO + (size_t)r * KDIM + kc + ch * 8; }
            cp16(base + t * TILEB + r * ROWB + ch * 16, src, v);
        }
    };

    auto compute = [&](int stage) {
        uint32_t aH = sb + stage * STAGEB;
        uint32_t aL = aH + TILEB;
        uint32_t bH = aH + 2 * TILEB;
        uint32_t bL = aH + 3 * TILEB;
        const int ar = lane & 15;
        const int ac = ((lane >> 4) & 1) * 8;
        const int br = ((lane >> 4) << 3) + (lane & 7);
        const int bc = ((lane >> 3) & 1) * 8;
#pragma unroll
        for (int k16 = 0; k16 < KC / 16; k16++) {
            uint32_t ah[4][4], al[4][4], bh[4][2], bl[4][2];
#pragma unroll
            for (int mf = 0; mf < 4; mf++) {
                uint32_t off = (uint32_t)((wm * 64 + mf * 16 + ar) * ROWB + (ac + k16 * 16) * 2);
                ldsm4(ah[mf], aH + off);
                ldsm4(al[mf], aL + off);
            }
#pragma unroll
            for (int np = 0; np < 2; np++) {
                uint32_t off = (uint32_t)((wn * 32 + np * 16 + br) * ROWB + (bc + k16 * 16) * 2);
                uint32_t t[4];
                ldsm4(t, bH + off);
                bh[np*2][0] = t[0]; bh[np*2][1] = t[1]; bh[np*2+1][0] = t[2]; bh[np*2+1][1] = t[3];
                ldsm4(t, bL + off);
                bl[np*2][0] = t[0]; bl[np*2][1] = t[1]; bl[np*2+1][0] = t[2]; bl[np*2+1][1] = t[3];
            }
#pragma unroll
            for (int mf = 0; mf < 4; mf++)
#pragma unroll
                for (int nf = 0; nf < 4; nf++) {
                    mma16816(acc[mf][nf], ah[mf], bh[nf]);
                    mma16816(acc[mf][nf], ah[mf], bl[nf]);
                    mma16816(acc[mf][nf], al[mf], bh[nf]);
                }
        }
    };

    constexpr int NIT = KDIM / KC;   // 4
    load_stage(0, 0);
    CP_COMMIT();
    for (int it = 0; it < NIT; it++) {
        if (it + 1 < NIT) {
            load_stage((it + 1) & 1, (it + 1) * KC);
            CP_COMMIT();
            asm volatile("cp.async.wait_group 1;" ::: "memory");
        } else {
            asm volatile("cp.async.wait_group 0;" ::: "memory");
        }
        __syncthreads();
        compute(it & 1);
        __syncthreads();
    }

    // ---- epilogue ----
#pragma unroll
    for (int mf = 0; mf < 4; mf++) {
        int rbase = m0 + wm * 64 + mf * 16 + (lane >> 2);
#pragma unroll
        for (int nf = 0; nf < 4; nf++) {
            int col = (HEAD ? 0 : n0) + wn * 32 + nf * 8 + (lane & 3) * 2;
#pragma unroll
            for (int h = 0; h < 2; h++) {
                int row = rbase + h * 8;
                if (row >= M) continue;
                float2 v = make_float2(acc[mf][nf][h * 2], acc[mf][nf][h * 2 + 1]);
                if (!HEAD) {
                    *(float2*)(out + (size_t)row * ldC + col) = v;
                } else {
                    v.x += g_headb[col]; v.y += g_headb[col + 1];
                    float* dst = (col < NCLASS)
                        ? out + (size_t)row * NCLASS + col
                        : out + (size_t)N_NODES * NCLASS + (size_t)row * NCLASS + (col - NCLASS);
                    *(float2*)dst = v;
                }
            }
        }
    }
}

// ---------------- SpMM + bias + relu -> bf16 hi/lo split ----------------
struct __align__(8) bf16x4 { __nv_bfloat162 a, b; };
__device__ __forceinline__ void emit4(__nv_bfloat16* Hh, __nv_bfloat16* Hl, size_t idx,
                                      float4 acc, float4 bia) {
    float v0 = fmaxf(acc.x + bia.x, 0.f), v1 = fmaxf(acc.y + bia.y, 0.f);
    float v2 = fmaxf(acc.z + bia.z, 0.f), v3 = fmaxf(acc.w + bia.w, 0.f);
    __nv_bfloat16 h0 = __float2bfloat16(v0), h1 = __float2bfloat16(v1);
    __nv_bfloat16 h2 = __float2bfloat16(v2), h3 = __float2bfloat16(v3);
    bf16x4 hv; hv.a = __nv_bfloat162(h0, h1); hv.b = __nv_bfloat162(h2, h3);
    *(bf16x4*)(Hh + idx) = hv;
    bf16x4 lv;
    lv.a = __nv_bfloat162(__float2bfloat16(v0 - __bfloat162float(h0)),
                          __float2bfloat16(v1 - __bfloat162float(h1)));
    lv.b = __nv_bfloat162(__float2bfloat16(v2 - __bfloat162float(h2)),
                          __float2bfloat16(v3 - __bfloat162float(h3)));
    *(bf16x4*)(Hl + idx) = lv;
}

__global__ void spmm_relu_kernel(const float* __restrict__ S, const int* __restrict__ src,
                                 const float* __restrict__ w, const float* __restrict__ bias,
                                 __nv_bfloat16* __restrict__ Hh, __nv_bfloat16* __restrict__ Hl) {
    int node = (blockIdx.x * blockDim.x + threadIdx.x) >> 5;
    if (node >= N_NODES) return;
    int lane = threadIdx.x & 31;
    int e0 = g_row_ptr[node], e1 = g_row_ptr[node + 1];

    float4 acc0 = make_float4(0.f, 0.f, 0.f, 0.f);
    float4 acc1 = make_float4(0.f, 0.f, 0.f, 0.f);
#pragma unroll 2
    for (int e = e0; e < e1; e++) {
        int   s  = __ldg(src + e);
        float ww = __ldg(w + e);
        const float4* row = (const float4*)(S + (size_t)s * NHID);
        float4 a = __ldg(row + lane);
        float4 b = __ldg(row + lane + 32);
        acc0.x += ww * a.x; acc0.y += ww * a.y; acc0.z += ww * a.z; acc0.w += ww * a.w;
        acc1.x += ww * b.x; acc1.y += ww * b.y; acc1.z += ww * b.z; acc1.w += ww * b.w;
    }
    const float4* bp = (const float4*)bias;
    emit4(Hh, Hl, (size_t)node * NHID + lane * 4, acc0, bp[lane]);
    emit4(Hh, Hl, (size_t)node * NHID + (lane + 32) * 4, acc1, bp[lane + 32]);
}

// ---------------- launch ----------------
extern "C" void kernel_launch(void* const* d_in, const int* in_sizes, int n_in,
                              void* d_out, int out_size) {
    const float* x   = (const float*)d_in[0];
    const int*   es  = (const int*)  d_in[1];
    const int*   ed  = (const int*)  d_in[2];
    const float* ew  = (const float*)d_in[3];
    const float* W1  = (const float*)d_in[4];
    const float* b1  = (const float*)d_in[5];
    const float* W2  = (const float*)d_in[6];
    const float* b2  = (const float*)d_in[7];
    const float* WL1 = (const float*)d_in[8];
    const float* bL1 = (const float*)d_in[9];
    const float* WL2 = (const float*)d_in[10];
    const float* bL2 = (const float*)d_in[11];
    int n_edges = in_sizes[1];

    float *S; __nv_bfloat16 *xh, *xl, *hh, *hl, *w1h, *w1l, *w2h, *w2l, *whh, *whl;
    cudaGetSymbolAddress((void**)&S,   g_S);
    cudaGetSymbolAddress((void**)&xh,  g_xh);    cudaGetSymbolAddress((void**)&xl,  g_xl);
    cudaGetSymbolAddress((void**)&hh,  g_hh);    cudaGetSymbolAddress((void**)&hl,  g_hl);
    cudaGetSymbolAddress((void**)&w1h, g_w1t_h); cudaGetSymbolAddress((void**)&w1l, g_w1t_l);
    cudaGetSymbolAddress((void**)&w2h, g_w2t_h); cudaGetSymbolAddress((void**)&w2l, g_w2t_l);
    cudaGetSymbolAddress((void**)&whh, g_wht_h); cudaGetSymbolAddress((void**)&whl, g_wht_l);

    cudaFuncSetAttribute(gemm_mma_kernel<false>,
                         cudaFuncAttributeMaxDynamicSharedMemorySize, GEMM_SMEM);
    cudaFuncSetAttribute(gemm_mma_kernel<true>,
                         cudaFuncAttributeMaxDynamicSharedMemorySize, GEMM_SMEM);

    const int MTILES = (N_NODES + 127) / 128;   // 782
    const int spmm_blocks = (N_NODES + 7) / 8;  // 8 warps/block

    build_row_ptr_kernel<<<(N_NODES + 256) / 256, 256>>>(ed, n_edges);
    prep_w_kernel<<<(KDIM * NHID + 255) / 256, 256>>>(W1, W2, WL1, WL2, bL1, bL2);
    convert_x_kernel<<<(N_NODES * NFEAT + 255) / 256, 256>>>(x);

    // layer 1
    gemm_mma_kernel<false><<<dim3(2, MTILES), 256, GEMM_SMEM>>>(xh, xl, w1h, w1l, S, N_NODES, NHID);
    spmm_relu_kernel<<<spmm_blocks, 256>>>(S, es, ew, b1, hh, hl);
    // layer 2
    gemm_mma_kernel<false><<<dim3(2, MTILES), 256, GEMM_SMEM>>>(hh, hl, w2h, w2l, S, N_NODES, NHID);
    spmm_relu_kernel<<<spmm_blocks, 256>>>(S, es, ew, b2, hh, hl);
    // twin heads
    gemm_mma_kernel<true><<<dim3(1, MTILES), 256, GEMM_SMEM>>>(hh, hl, whh, whl, (float*)d_out, N_NODES, 128);
}